// round 7
// baseline (speedup 1.0000x reference)
#include <cuda_runtime.h>
#include <cuda_bf16.h>
#include <cstdint>
#include <math.h>

// Problem dims (fixed by the dataset)
#define T_STEPS 512
#define B_SZ    64
#define D_SZ    256
#define H_SZ    256
#define ALPHA   0.9f

// Scratch for the precomputed input GEMM: xw[t][b][h] = inputs[t,b,:]@W_in + b
__device__ float g_xw[(size_t)T_STEPS * B_SZ * H_SZ];

// ---- f32x2 helpers (sm_103a packed fp32 FMA) --------------------------------
__device__ __forceinline__ unsigned long long pk2(float lo, float hi) {
    unsigned long long r;
    asm("mov.b64 %0, {%1, %2};" : "=l"(r) : "f"(lo), "f"(hi));
    return r;
}
__device__ __forceinline__ unsigned long long dup2(float a) {
    unsigned long long r;
    asm("mov.b64 %0, {%1, %1};" : "=l"(r) : "f"(a));
    return r;
}
__device__ __forceinline__ void fma2(unsigned long long& acc,
                                     unsigned long long a, unsigned long long b) {
    asm("fma.rn.f32x2 %0, %1, %2, %0;" : "+l"(acc) : "l"(a), "l"(b));
}
__device__ __forceinline__ float2 unpk(unsigned long long v) {
    float lo, hi;
    asm("mov.b64 {%0, %1}, %2;" : "=f"(lo), "=f"(hi) : "l"(v));
    return make_float2(lo, hi);
}

// ---------------------------------------------------------------------------
// Tiled fp32 GEMM with FFMA2: C[M,256] = A[M,256] @ Bm[256,256] (+ bias).
// Tiles 128x128, BK=8, 256 threads, 8x8 per thread (as 8x4 f32x2 accs).
// ---------------------------------------------------------------------------
__global__ __launch_bounds__(256) void sgemm_k(
    const float* __restrict__ A, const float* __restrict__ Bm,
    const float* __restrict__ bias, float* __restrict__ C)
{
    const int K = 256, N = 256;
    __shared__ float As[2][8][128];
    __shared__ float Bs[2][8][128];

    const int tid = threadIdx.x;
    const int bm = blockIdx.x * 128;
    const int bn = blockIdx.y * 128;
    const int tx = tid & 15;
    const int ty = tid >> 4;

    const int a_m = tid >> 1;
    const int a_k = (tid & 1) * 4;
    const int b_k = tid >> 5;
    const int b_n = (tid & 31) * 4;

    const float* Ap = A + (size_t)(bm + a_m) * K + a_k;
    const float* Bp = Bm + (size_t)b_k * N + bn + b_n;

    float4 af = *(const float4*)Ap;
    float4 bf = *(const float4*)Bp;

    unsigned long long acc2[8][4];
#pragma unroll
    for (int i = 0; i < 8; i++)
#pragma unroll
        for (int j = 0; j < 4; j++) acc2[i][j] = 0ull;

    int buf = 0;
    for (int kt = 0; kt < K; kt += 8) {
        As[buf][a_k + 0][a_m] = af.x;
        As[buf][a_k + 1][a_m] = af.y;
        As[buf][a_k + 2][a_m] = af.z;
        As[buf][a_k + 3][a_m] = af.w;
        *(float4*)&Bs[buf][b_k][b_n] = bf;
        __syncthreads();
        if (kt + 8 < K) {
            af = *(const float4*)(Ap + kt + 8);
            bf = *(const float4*)(Bp + (size_t)(kt + 8) * N);
        }
#pragma unroll
        for (int k = 0; k < 8; k++) {
            float4 a0 = *(const float4*)&As[buf][k][ty * 4];
            float4 a1 = *(const float4*)&As[buf][k][64 + ty * 4];
            ulonglong2 bx0 = *(const ulonglong2*)&Bs[buf][k][tx * 4];
            ulonglong2 bx1 = *(const ulonglong2*)&Bs[buf][k][64 + tx * 4];
            float av[8] = {a0.x, a0.y, a0.z, a0.w, a1.x, a1.y, a1.z, a1.w};
#pragma unroll
            for (int i = 0; i < 8; i++) {
                unsigned long long ad = dup2(av[i]);
                fma2(acc2[i][0], ad, bx0.x);
                fma2(acc2[i][1], ad, bx0.y);
                fma2(acc2[i][2], ad, bx1.x);
                fma2(acc2[i][3], ad, bx1.y);
            }
        }
        buf ^= 1;
    }

    float bv0[4], bv1[4];
#pragma unroll
    for (int j = 0; j < 4; j++) {
        bv0[j] = bias ? bias[bn + tx * 4 + j]      : 0.f;
        bv1[j] = bias ? bias[bn + 64 + tx * 4 + j] : 0.f;
    }

#pragma unroll
    for (int i = 0; i < 8; i++) {
        int r = bm + ((i < 4) ? (ty * 4 + i) : (64 + ty * 4 + (i - 4)));
        float2 p0 = unpk(acc2[i][0]), p1 = unpk(acc2[i][1]);
        float2 p2 = unpk(acc2[i][2]), p3 = unpk(acc2[i][3]);
        float4 o0, o1;
        o0.x = p0.x + bv0[0]; o0.y = p0.y + bv0[1];
        o0.z = p1.x + bv0[2]; o0.w = p1.y + bv0[3];
        o1.x = p2.x + bv1[0]; o1.y = p2.y + bv1[1];
        o1.z = p3.x + bv1[2]; o1.w = p3.y + bv1[3];
        *(float4*)&C[(size_t)r * N + bn + tx * 4]      = o0;
        *(float4*)&C[(size_t)r * N + bn + 64 + tx * 4] = o1;
    }
}

// ---------------------------------------------------------------------------
// Sequential scan: 64 CTAs (one per batch row), 512 threads.
// Thread: col = tid>>1, kh = tid&1 -> k range [kh*128, kh*128+128).
// Per column the two k-half partials are combined with shfl.xor(1) (adjacent
// lanes). W: 48 pairs/thread in registers + 16 pairs/thread in smem.
// Spike vector double-buffered in smem; ONE __syncthreads per step.
// ---------------------------------------------------------------------------
#define RP 48   // register-resident W pairs per thread (96 k-rows)
#define SP 16   // smem-resident W pairs per thread   (32 k-rows)

__global__ __launch_bounds__(512, 1) void scan_kernel(
    const float* __restrict__ W_rec, const float* __restrict__ spike0,
    const float* __restrict__ v0,    const float* __restrict__ xw,
    float* __restrict__ spikes, float* __restrict__ probs,
    float* __restrict__ vT, float* __restrict__ sT)
{
    extern __shared__ __align__(16) unsigned char dynsm[];
    unsigned long long* w2 = (unsigned long long*)dynsm;     // [SP*512]
    float* sbuf = (float*)(w2 + SP * 512);                   // [2][256]

    const int tid = threadIdx.x;
    const int col = tid >> 1;        // output column
    const int kh  = tid & 1;         // k-half
    const int row = blockIdx.x;      // batch row
    const int kbase = kh * 128;

    // smem W pairs: rows [kbase+2*RP, kbase+128)
#pragma unroll
    for (int j = 0; j < SP; j++)
        w2[j * 512 + tid] = pk2(W_rec[(size_t)(kbase + 2 * RP + 2 * j) * 256 + col],
                                W_rec[(size_t)(kbase + 2 * RP + 2 * j + 1) * 256 + col]);

    // register W pairs: rows [kbase, kbase+2*RP)
    unsigned long long wreg[RP];
#pragma unroll
    for (int j = 0; j < RP; j++)
        wreg[j] = pk2(W_rec[(size_t)(kbase + 2 * j) * 256 + col],
                      W_rec[(size_t)(kbase + 2 * j + 1) * 256 + col]);

    if (tid < 256) {
        const float s0 = spike0[row * 256 + tid];
        sbuf[tid] = s0;
        spikes[(size_t)row * 256 + tid] = s0;    // spikes[0] = spike0
    }

    float v = 0.f, prob = 0.f;
    if (kh == 0) {
        v = v0[row * 256 + col];
        prob = spike0[row * 256 + col];
    }

    const float* xwp = xw + (size_t)row * 256 + col;   // kh==0 only
    float xnext = (kh == 0) ? __ldg(xwp) : 0.f;

    __syncthreads();

    int cur = 0;
    for (int step = 0; step < T_STEPS; step++) {
        const float xval = xnext;
        if (kh == 0 && step + 1 < T_STEPS)
            xnext = __ldg(xwp + (size_t)(step + 1) * (B_SZ * H_SZ));

        unsigned long long a4[4] = {0ull, 0ull, 0ull, 0ull};
        const ulonglong2* sp = (const ulonglong2*)&sbuf[cur * 256 + kbase];

        // Register part: pairs 0..2*RP/2-1  (RP FFMA2, RP/2 LDS.128 of s)
#pragma unroll
        for (int q = 0; q < RP / 2; q++) {
            ulonglong2 sv = sp[q];
            fma2(a4[(2 * q) & 3],     wreg[2 * q],     sv.x);
            fma2(a4[(2 * q + 1) & 3], wreg[2 * q + 1], sv.y);
        }
        // Smem part: pairs RP..RP+SP-1
#pragma unroll
        for (int q = 0; q < SP / 2; q++) {
            ulonglong2 sv = sp[RP / 2 + q];
            fma2(a4[0], w2[(2 * q) * 512 + tid],     sv.x);
            fma2(a4[1], w2[(2 * q + 1) * 512 + tid], sv.y);
        }

        float2 q0 = unpk(a4[0]), q1 = unpk(a4[1]), q2 = unpk(a4[2]), q3 = unpk(a4[3]);
        float acc = ((q0.x + q0.y) + (q1.x + q1.y)) + ((q2.x + q2.y) + (q3.x + q3.y));

        // Combine k-halves: partner is the adjacent lane
        acc += __shfl_xor_sync(0xffffffffu, acc, 1);

        const int nxt = cur ^ 1;
        if (kh == 0) {
            v = ALPHA * v + xval + acc;
            prob = 1.0f / (1.0f + __expf(-v));

            const size_t off = ((size_t)step * B_SZ + row) * 256 + col;
            probs[off] = prob;                        // probs[step]
            spikes[off + (size_t)B_SZ * 256] = prob;  // spikes[step+1]

            sbuf[nxt * 256 + col] = prob;
        }
        __syncthreads();   // new spikes visible; all reads of cur done
        cur = nxt;
    }

    if (kh == 0) {
        vT[row * 256 + col] = v;
        sT[row * 256 + col] = prob;
    }
}

// ---------------------------------------------------------------------------
// Launch: GEMM(xw) -> scan -> GEMM(preds). All stream-ordered, capture-safe.
// ---------------------------------------------------------------------------
extern "C" void kernel_launch(void* const* d_in, const int* in_sizes, int n_in,
                              void* d_out, int out_size)
{
    const float* inputs = (const float*)d_in[0];  // [512,64,256]
    const float* spike0 = (const float*)d_in[1];  // [64,256]
    const float* v0     = (const float*)d_in[2];  // [64,256]
    const float* W_in   = (const float*)d_in[3];  // [256,256]
    const float* W_rec  = (const float*)d_in[4];  // [256,256]
    const float* W_out  = (const float*)d_in[5];  // [256,256]
    const float* bvec   = (const float*)d_in[6];  // [256]

    float* out = (float*)d_out;
    float* spikes = out;
    float* preds  = out + (size_t)513 * B_SZ * H_SZ;
    float* probs  = preds + (size_t)T_STEPS * B_SZ * H_SZ;
    float* vT     = probs + (size_t)T_STEPS * B_SZ * H_SZ;
    float* sT     = vT + (size_t)B_SZ * H_SZ;

    float* xw = nullptr;
    cudaGetSymbolAddress((void**)&xw, g_xw);

    const size_t scan_smem = (size_t)SP * 512 * 8 + 2 * 256 * sizeof(float);
    cudaFuncSetAttribute(scan_kernel, cudaFuncAttributeMaxDynamicSharedMemorySize,
                         (int)scan_smem);

    dim3 gemm_grid((T_STEPS * B_SZ) / 128, H_SZ / 128);  // (256, 2)

    // 1) xw = inputs @ W_in + b
    sgemm_k<<<gemm_grid, 256>>>(inputs, W_in, bvec, xw);

    // 2) sequential scan (64 CTAs, one per batch row, 512 threads)
    scan_kernel<<<B_SZ, 512, scan_smem>>>(W_rec, spike0, v0, xw,
                                          spikes, probs, vT, sT);

    // 3) preds = spikes[1:] @ W_out
    sgemm_k<<<gemm_grid, 256>>>(spikes + (size_t)B_SZ * H_SZ, W_out, nullptr, preds);
}

// round 8
// speedup vs baseline: 1.3376x; 1.3376x over previous
#include <cuda_runtime.h>
#include <cuda_bf16.h>
#include <cstdint>
#include <math.h>

// Problem dims (fixed by the dataset)
#define T_STEPS 512
#define B_SZ    64
#define D_SZ    256
#define H_SZ    256
#define ALPHA   0.9f

// Scratch for the precomputed input GEMM: xw[t][b][h] = inputs[t,b,:]@W_in + b
__device__ float g_xw[(size_t)T_STEPS * B_SZ * H_SZ];

// ---- f32x2 helpers (sm_103a packed fp32 FMA) --------------------------------
__device__ __forceinline__ unsigned long long pk2(float lo, float hi) {
    unsigned long long r;
    asm("mov.b64 %0, {%1, %2};" : "=l"(r) : "f"(lo), "f"(hi));
    return r;
}
__device__ __forceinline__ unsigned long long dup2(float a) {
    unsigned long long r;
    asm("mov.b64 %0, {%1, %1};" : "=l"(r) : "f"(a));
    return r;
}
__device__ __forceinline__ void fma2(unsigned long long& acc,
                                     unsigned long long a, unsigned long long b) {
    asm("fma.rn.f32x2 %0, %1, %2, %0;" : "+l"(acc) : "l"(a), "l"(b));
}
__device__ __forceinline__ float2 unpk(unsigned long long v) {
    float lo, hi;
    asm("mov.b64 {%0, %1}, %2;" : "=f"(lo), "=f"(hi) : "l"(v));
    return make_float2(lo, hi);
}

// ---------------------------------------------------------------------------
// Tiled fp32 GEMM with FFMA2: C[M,256] = A[M,256] @ Bm[256,256] (+ bias).
// Tiles 128x128, BK=8, 256 threads, 8x8 per thread (as 8x4 f32x2 accs).
// ---------------------------------------------------------------------------
__global__ __launch_bounds__(256) void sgemm_k(
    const float* __restrict__ A, const float* __restrict__ Bm,
    const float* __restrict__ bias, float* __restrict__ C)
{
    const int K = 256, N = 256;
    __shared__ float As[2][8][128];
    __shared__ float Bs[2][8][128];

    const int tid = threadIdx.x;
    const int bm = blockIdx.x * 128;
    const int bn = blockIdx.y * 128;
    const int tx = tid & 15;
    const int ty = tid >> 4;

    const int a_m = tid >> 1;
    const int a_k = (tid & 1) * 4;
    const int b_k = tid >> 5;
    const int b_n = (tid & 31) * 4;

    const float* Ap = A + (size_t)(bm + a_m) * K + a_k;
    const float* Bp = Bm + (size_t)b_k * N + bn + b_n;

    float4 af = *(const float4*)Ap;
    float4 bf = *(const float4*)Bp;

    unsigned long long acc2[8][4];
#pragma unroll
    for (int i = 0; i < 8; i++)
#pragma unroll
        for (int j = 0; j < 4; j++) acc2[i][j] = 0ull;

    int buf = 0;
    for (int kt = 0; kt < K; kt += 8) {
        As[buf][a_k + 0][a_m] = af.x;
        As[buf][a_k + 1][a_m] = af.y;
        As[buf][a_k + 2][a_m] = af.z;
        As[buf][a_k + 3][a_m] = af.w;
        *(float4*)&Bs[buf][b_k][b_n] = bf;
        __syncthreads();
        if (kt + 8 < K) {
            af = *(const float4*)(Ap + kt + 8);
            bf = *(const float4*)(Bp + (size_t)(kt + 8) * N);
        }
#pragma unroll
        for (int k = 0; k < 8; k++) {
            float4 a0 = *(const float4*)&As[buf][k][ty * 4];
            float4 a1 = *(const float4*)&As[buf][k][64 + ty * 4];
            ulonglong2 bx0 = *(const ulonglong2*)&Bs[buf][k][tx * 4];
            ulonglong2 bx1 = *(const ulonglong2*)&Bs[buf][k][64 + tx * 4];
            float av[8] = {a0.x, a0.y, a0.z, a0.w, a1.x, a1.y, a1.z, a1.w};
#pragma unroll
            for (int i = 0; i < 8; i++) {
                unsigned long long ad = dup2(av[i]);
                fma2(acc2[i][0], ad, bx0.x);
                fma2(acc2[i][1], ad, bx0.y);
                fma2(acc2[i][2], ad, bx1.x);
                fma2(acc2[i][3], ad, bx1.y);
            }
        }
        buf ^= 1;
    }

    float bv0[4], bv1[4];
#pragma unroll
    for (int j = 0; j < 4; j++) {
        bv0[j] = bias ? bias[bn + tx * 4 + j]      : 0.f;
        bv1[j] = bias ? bias[bn + 64 + tx * 4 + j] : 0.f;
    }

#pragma unroll
    for (int i = 0; i < 8; i++) {
        int r = bm + ((i < 4) ? (ty * 4 + i) : (64 + ty * 4 + (i - 4)));
        float2 p0 = unpk(acc2[i][0]), p1 = unpk(acc2[i][1]);
        float2 p2 = unpk(acc2[i][2]), p3 = unpk(acc2[i][3]);
        float4 o0, o1;
        o0.x = p0.x + bv0[0]; o0.y = p0.y + bv0[1];
        o0.z = p1.x + bv0[2]; o0.w = p1.y + bv0[3];
        o1.x = p2.x + bv1[0]; o1.y = p2.y + bv1[1];
        o1.z = p3.x + bv1[2]; o1.w = p3.y + bv1[3];
        *(float4*)&C[(size_t)r * N + bn + tx * 4]      = o0;
        *(float4*)&C[(size_t)r * N + bn + 64 + tx * 4] = o1;
    }
}

// ---------------------------------------------------------------------------
// Sequential scan: 64 CTAs (one per batch row), 256 threads (thread = column).
// W_rec rows [0,208) register-resident as 104 f32x2 per thread; rows [208,256)
// in smem PRE-PACKED as f32x2 pairs so the dot is pure FFMA2.
// Spike vector double-buffered in smem; ONE __syncthreads per step.
// ---------------------------------------------------------------------------
#define WREG_PAIRS 104   // 208 rows in registers
#define WSM_PAIRS  24    // 48 rows in smem (24 packed pairs)

__global__ __launch_bounds__(256, 1) void scan_kernel(
    const float* __restrict__ W_rec, const float* __restrict__ spike0,
    const float* __restrict__ v0,    const float* __restrict__ xw,
    float* __restrict__ spikes, float* __restrict__ probs,
    float* __restrict__ vT, float* __restrict__ sT)
{
    extern __shared__ __align__(16) unsigned char dynsm[];
    unsigned long long* w2 = (unsigned long long*)dynsm;     // [WSM_PAIRS*256]
    float* sbuf = (float*)(w2 + WSM_PAIRS * 256);            // [2][256]

    const int t   = threadIdx.x;   // output column
    const int row = blockIdx.x;    // batch row

    // Stage smem W pairs: w2[j*256+t] = (W[208+2j][t], W[209+2j][t])
#pragma unroll
    for (int j = 0; j < WSM_PAIRS; j++)
        w2[j * 256 + t] = pk2(W_rec[(size_t)(2 * WREG_PAIRS + 2 * j) * 256 + t],
                              W_rec[(size_t)(2 * WREG_PAIRS + 2 * j + 1) * 256 + t]);

    // Register-resident W pairs: rows [0,208)
    unsigned long long wpk[WREG_PAIRS];
#pragma unroll
    for (int j = 0; j < WREG_PAIRS; j++)
        wpk[j] = pk2(W_rec[(size_t)(2 * j) * 256 + t],
                     W_rec[(size_t)(2 * j + 1) * 256 + t]);

    const float s0 = spike0[row * 256 + t];
    sbuf[t] = s0;
    spikes[(size_t)row * 256 + t] = s0;          // spikes[0] = spike0
    float v = v0[row * 256 + t];
    float prob = s0;

    const float* xwp = xw + (size_t)row * 256 + t;
    float xnext = __ldg(xwp);

    __syncthreads();

    int cur = 0;
    for (int step = 0; step < T_STEPS; step++) {
        const float xval = xnext;
        if (step + 1 < T_STEPS)
            xnext = __ldg(xwp + (size_t)(step + 1) * (B_SZ * H_SZ));

        unsigned long long a4[4] = {0ull, 0ull, 0ull, 0ull};

        // Register part: k in [0,208), 52 LDS.128 of s, 104 FFMA2
        const ulonglong2* sp = (const ulonglong2*)&sbuf[cur * 256];
#pragma unroll
        for (int q = 0; q < WREG_PAIRS / 2; q++) {
            ulonglong2 sv = sp[q];
            fma2(a4[(2 * q) & 3],     wpk[2 * q],     sv.x);
            fma2(a4[(2 * q + 1) & 3], wpk[2 * q + 1], sv.y);
        }
        // Smem part: k in [208,256), W pairs from smem (LDS.64), 24 FFMA2
        const ulonglong2* sp2 = (const ulonglong2*)&sbuf[cur * 256 + 2 * WREG_PAIRS];
#pragma unroll
        for (int q = 0; q < WSM_PAIRS / 2; q++) {
            ulonglong2 sv = sp2[q];
            fma2(a4[0], w2[(2 * q) * 256 + t],     sv.x);
            fma2(a4[1], w2[(2 * q + 1) * 256 + t], sv.y);
        }

        float2 q0 = unpk(a4[0]), q1 = unpk(a4[1]), q2 = unpk(a4[2]), q3 = unpk(a4[3]);
        float acc = ((q0.x + q0.y) + (q1.x + q1.y)) + ((q2.x + q2.y) + (q3.x + q3.y));

        v = ALPHA * v + xval + acc;
        prob = 1.0f / (1.0f + __expf(-v));

        const size_t off = ((size_t)step * B_SZ + row) * 256 + t;
        probs[off] = prob;                        // probs[step]
        spikes[off + (size_t)B_SZ * 256] = prob;  // spikes[step+1]

        const int nxt = cur ^ 1;
        sbuf[nxt * 256 + t] = prob;
        __syncthreads();   // writes to nxt visible; prior reads of cur done
        cur = nxt;
    }

    vT[row * 256 + t] = v;
    sT[row * 256 + t] = prob;
}

// Trailing no-op launch: realigns ncu's "-s 5 -c 1" capture so that the 6th
// launch in the run is scan_kernel (4 launches per kernel_launch call).
__global__ void align_dummy_k(float* p) {
    if (threadIdx.x == 1u << 30) p[0] = 0.f;   // never true; prevents DCE
}

// ---------------------------------------------------------------------------
// Launch: GEMM(xw) -> scan -> GEMM(preds) -> dummy. Capture-safe.
// ---------------------------------------------------------------------------
extern "C" void kernel_launch(void* const* d_in, const int* in_sizes, int n_in,
                              void* d_out, int out_size)
{
    const float* inputs = (const float*)d_in[0];  // [512,64,256]
    const float* spike0 = (const float*)d_in[1];  // [64,256]
    const float* v0     = (const float*)d_in[2];  // [64,256]
    const float* W_in   = (const float*)d_in[3];  // [256,256]
    const float* W_rec  = (const float*)d_in[4];  // [256,256]
    const float* W_out  = (const float*)d_in[5];  // [256,256]
    const float* bvec   = (const float*)d_in[6];  // [256]

    float* out = (float*)d_out;
    float* spikes = out;
    float* preds  = out + (size_t)513 * B_SZ * H_SZ;
    float* probs  = preds + (size_t)T_STEPS * B_SZ * H_SZ;
    float* vT     = probs + (size_t)T_STEPS * B_SZ * H_SZ;
    float* sT     = vT + (size_t)B_SZ * H_SZ;

    float* xw = nullptr;
    cudaGetSymbolAddress((void**)&xw, g_xw);

    const size_t scan_smem = (size_t)WSM_PAIRS * 256 * 8 + 2 * 256 * sizeof(float);
    cudaFuncSetAttribute(scan_kernel, cudaFuncAttributeMaxDynamicSharedMemorySize,
                         (int)scan_smem);

    dim3 gemm_grid((T_STEPS * B_SZ) / 128, H_SZ / 128);  // (256, 2)

    // 1) xw = inputs @ W_in + b
    sgemm_k<<<gemm_grid, 256>>>(inputs, W_in, bvec, xw);

    // 2) sequential scan (64 CTAs, one per batch row)
    scan_kernel<<<B_SZ, 256, scan_smem>>>(W_rec, spike0, v0, xw,
                                          spikes, probs, vT, sT);

    // 3) preds = spikes[1:] @ W_out
    sgemm_k<<<gemm_grid, 256>>>(spikes + (size_t)B_SZ * H_SZ, W_out, nullptr, preds);

    // 4) ncu alignment dummy (no-op)
    align_dummy_k<<<1, 32>>>(xw);
}

// round 9
// speedup vs baseline: 1.5810x; 1.1820x over previous
#include <cuda_runtime.h>
#include <cuda_bf16.h>
#include <cstdint>
#include <math.h>

// Problem dims (fixed by the dataset)
#define T_STEPS 512
#define B_SZ    64
#define D_SZ    256
#define H_SZ    256
#define ALPHA   0.9f

// Scratch for the precomputed input GEMM: xw[t][b][h] = inputs[t,b,:]@W_in + b
__device__ float g_xw[(size_t)T_STEPS * B_SZ * H_SZ];

// ---- f32x2 helpers (sm_103a packed fp32 FMA) --------------------------------
__device__ __forceinline__ unsigned long long pk2(float lo, float hi) {
    unsigned long long r;
    asm("mov.b64 %0, {%1, %2};" : "=l"(r) : "f"(lo), "f"(hi));
    return r;
}
__device__ __forceinline__ unsigned long long dup2(float a) {
    unsigned long long r;
    asm("mov.b64 %0, {%1, %1};" : "=l"(r) : "f"(a));
    return r;
}
__device__ __forceinline__ void fma2(unsigned long long& acc,
                                     unsigned long long a, unsigned long long b) {
    asm("fma.rn.f32x2 %0, %1, %2, %0;" : "+l"(acc) : "l"(a), "l"(b));
}
__device__ __forceinline__ float2 unpk(unsigned long long v) {
    float lo, hi;
    asm("mov.b64 {%0, %1}, %2;" : "=f"(lo), "=f"(hi) : "l"(v));
    return make_float2(lo, hi);
}

// ---------------------------------------------------------------------------
// Tiled fp32 GEMM with FFMA2: C[M,256] = A[M,256] @ Bm[256,256] (+ bias).
// Tiles 128x128, BK=8, 256 threads, 8x8 per thread (as 8x4 f32x2 accs).
// ---------------------------------------------------------------------------
__global__ __launch_bounds__(256) void sgemm_k(
    const float* __restrict__ A, const float* __restrict__ Bm,
    const float* __restrict__ bias, float* __restrict__ C)
{
    const int K = 256, N = 256;
    __shared__ float As[2][8][128];
    __shared__ float Bs[2][8][128];

    const int tid = threadIdx.x;
    const int bm = blockIdx.x * 128;
    const int bn = blockIdx.y * 128;
    const int tx = tid & 15;
    const int ty = tid >> 4;

    const int a_m = tid >> 1;
    const int a_k = (tid & 1) * 4;
    const int b_k = tid >> 5;
    const int b_n = (tid & 31) * 4;

    const float* Ap = A + (size_t)(bm + a_m) * K + a_k;
    const float* Bp = Bm + (size_t)b_k * N + bn + b_n;

    float4 af = *(const float4*)Ap;
    float4 bf = *(const float4*)Bp;

    unsigned long long acc2[8][4];
#pragma unroll
    for (int i = 0; i < 8; i++)
#pragma unroll
        for (int j = 0; j < 4; j++) acc2[i][j] = 0ull;

    int buf = 0;
    for (int kt = 0; kt < K; kt += 8) {
        As[buf][a_k + 0][a_m] = af.x;
        As[buf][a_k + 1][a_m] = af.y;
        As[buf][a_k + 2][a_m] = af.z;
        As[buf][a_k + 3][a_m] = af.w;
        *(float4*)&Bs[buf][b_k][b_n] = bf;
        __syncthreads();
        if (kt + 8 < K) {
            af = *(const float4*)(Ap + kt + 8);
            bf = *(const float4*)(Bp + (size_t)(kt + 8) * N);
        }
#pragma unroll
        for (int k = 0; k < 8; k++) {
            float4 a0 = *(const float4*)&As[buf][k][ty * 4];
            float4 a1 = *(const float4*)&As[buf][k][64 + ty * 4];
            ulonglong2 bx0 = *(const ulonglong2*)&Bs[buf][k][tx * 4];
            ulonglong2 bx1 = *(const ulonglong2*)&Bs[buf][k][64 + tx * 4];
            float av[8] = {a0.x, a0.y, a0.z, a0.w, a1.x, a1.y, a1.z, a1.w};
#pragma unroll
            for (int i = 0; i < 8; i++) {
                unsigned long long ad = dup2(av[i]);
                fma2(acc2[i][0], ad, bx0.x);
                fma2(acc2[i][1], ad, bx0.y);
                fma2(acc2[i][2], ad, bx1.x);
                fma2(acc2[i][3], ad, bx1.y);
            }
        }
        buf ^= 1;
    }

    float bv0[4], bv1[4];
#pragma unroll
    for (int j = 0; j < 4; j++) {
        bv0[j] = bias ? bias[bn + tx * 4 + j]      : 0.f;
        bv1[j] = bias ? bias[bn + 64 + tx * 4 + j] : 0.f;
    }

#pragma unroll
    for (int i = 0; i < 8; i++) {
        int r = bm + ((i < 4) ? (ty * 4 + i) : (64 + ty * 4 + (i - 4)));
        float2 p0 = unpk(acc2[i][0]), p1 = unpk(acc2[i][1]);
        float2 p2 = unpk(acc2[i][2]), p3 = unpk(acc2[i][3]);
        float4 o0, o1;
        o0.x = p0.x + bv0[0]; o0.y = p0.y + bv0[1];
        o0.z = p1.x + bv0[2]; o0.w = p1.y + bv0[3];
        o1.x = p2.x + bv1[0]; o1.y = p2.y + bv1[1];
        o1.z = p3.x + bv1[2]; o1.w = p3.y + bv1[3];
        *(float4*)&C[(size_t)r * N + bn + tx * 4]      = o0;
        *(float4*)&C[(size_t)r * N + bn + 64 + tx * 4] = o1;
    }
}

// ---------------------------------------------------------------------------
// Sequential scan: 64 CTAs (one per batch row), 256 threads (thread = column).
// W_rec rows [0,192) register-resident as 96 f32x2 per thread; rows [192,256)
// in smem PRE-PACKED as f32x2 pairs so the dot is pure FFMA2.
// Spike vector double-buffered in smem; ONE __syncthreads per step.
// ---------------------------------------------------------------------------
#define WREG_PAIRS 96    // 192 rows in registers
#define WSM_PAIRS  32    // 64 rows in smem (32 packed pairs)

__global__ __launch_bounds__(256, 1) void scan_kernel(
    const float* __restrict__ W_rec, const float* __restrict__ spike0,
    const float* __restrict__ v0,    const float* __restrict__ xw,
    float* __restrict__ spikes, float* __restrict__ probs,
    float* __restrict__ vT, float* __restrict__ sT)
{
    extern __shared__ __align__(16) unsigned char dynsm[];
    unsigned long long* w2 = (unsigned long long*)dynsm;              // [32*256] packed W pairs
    float* sbuf = (float*)(w2 + WSM_PAIRS * 256);                     // [2][256]

    const int t   = threadIdx.x;   // output column
    const int row = blockIdx.x;    // batch row

    // Stage smem W pairs: w2[j*256+t] = (W[192+2j][t], W[193+2j][t])
#pragma unroll
    for (int j = 0; j < WSM_PAIRS; j++)
        w2[j * 256 + t] = pk2(W_rec[(size_t)(2 * WREG_PAIRS + 2 * j) * 256 + t],
                              W_rec[(size_t)(2 * WREG_PAIRS + 2 * j + 1) * 256 + t]);

    // Register-resident W pairs: rows [0,192)
    unsigned long long wpk[WREG_PAIRS];
#pragma unroll
    for (int j = 0; j < WREG_PAIRS; j++)
        wpk[j] = pk2(W_rec[(size_t)(2 * j) * 256 + t],
                     W_rec[(size_t)(2 * j + 1) * 256 + t]);

    const float s0 = spike0[row * 256 + t];
    sbuf[t] = s0;
    spikes[(size_t)row * 256 + t] = s0;          // spikes[0] = spike0
    float v = v0[row * 256 + t];
    float prob = s0;

    const float* xwp = xw + (size_t)row * 256 + t;
    float xnext = __ldg(xwp);

    __syncthreads();

    int cur = 0;
    for (int step = 0; step < T_STEPS; step++) {
        const float xval = xnext;
        if (step + 1 < T_STEPS)
            xnext = __ldg(xwp + (size_t)(step + 1) * (B_SZ * H_SZ));

        unsigned long long a4[4] = {0ull, 0ull, 0ull, 0ull};

        // Register part: k in [0,192), 48 LDS.128 of s, 96 FFMA2
        const ulonglong2* sp = (const ulonglong2*)&sbuf[cur * 256];
#pragma unroll
        for (int q = 0; q < WREG_PAIRS / 2; q++) {
            ulonglong2 sv = sp[q];
            fma2(a4[(2 * q) & 3],     wpk[2 * q],     sv.x);
            fma2(a4[(2 * q + 1) & 3], wpk[2 * q + 1], sv.y);
        }
        // Smem part: k in [192,256), W pairs from smem (LDS.64), 32 FFMA2
        const ulonglong2* sp2 = (const ulonglong2*)&sbuf[cur * 256 + 2 * WREG_PAIRS];
#pragma unroll
        for (int q = 0; q < WSM_PAIRS / 2; q++) {
            ulonglong2 sv = sp2[q];
            fma2(a4[0], w2[(2 * q) * 256 + t],     sv.x);
            fma2(a4[1], w2[(2 * q + 1) * 256 + t], sv.y);
        }

        float2 q0 = unpk(a4[0]), q1 = unpk(a4[1]), q2 = unpk(a4[2]), q3 = unpk(a4[3]);
        float acc = ((q0.x + q0.y) + (q1.x + q1.y)) + ((q2.x + q2.y) + (q3.x + q3.y));

        v = ALPHA * v + xval + acc;
        prob = 1.0f / (1.0f + __expf(-v));

        const size_t off = ((size_t)step * B_SZ + row) * 256 + t;
        probs[off] = prob;                        // probs[step]
        spikes[off + (size_t)B_SZ * 256] = prob;  // spikes[step+1]

        const int nxt = cur ^ 1;
        sbuf[nxt * 256 + t] = prob;
        __syncthreads();   // writes to nxt visible; prior reads of cur done
        cur = nxt;
    }

    vT[row * 256 + t] = v;
    sT[row * 256 + t] = prob;
}

// No-op alignment kernel: with the harness contributing 2 launches before
// ours, placing scan_kernel at call-position 4 makes it ncu's launch #6.
__global__ void align_dummy_k(float* p) {
    if (threadIdx.x == 1u << 30) p[0] = 0.f;   // never true; prevents DCE
}

// ---------------------------------------------------------------------------
// Launch: sgemm(xw) -> dummy -> dummy -> scan -> sgemm(preds). Capture-safe.
// ---------------------------------------------------------------------------
extern "C" void kernel_launch(void* const* d_in, const int* in_sizes, int n_in,
                              void* d_out, int out_size)
{
    const float* inputs = (const float*)d_in[0];  // [512,64,256]
    const float* spike0 = (const float*)d_in[1];  // [64,256]
    const float* v0     = (const float*)d_in[2];  // [64,256]
    const float* W_in   = (const float*)d_in[3];  // [256,256]
    const float* W_rec  = (const float*)d_in[4];  // [256,256]
    const float* W_out  = (const float*)d_in[5];  // [256,256]
    const float* bvec   = (const float*)d_in[6];  // [256]

    float* out = (float*)d_out;
    float* spikes = out;
    float* preds  = out + (size_t)513 * B_SZ * H_SZ;
    float* probs  = preds + (size_t)T_STEPS * B_SZ * H_SZ;
    float* vT     = probs + (size_t)T_STEPS * B_SZ * H_SZ;
    float* sT     = vT + (size_t)B_SZ * H_SZ;

    float* xw = nullptr;
    cudaGetSymbolAddress((void**)&xw, g_xw);

    const size_t scan_smem = (size_t)WSM_PAIRS * 256 * 8 + 2 * 256 * sizeof(float);
    cudaFuncSetAttribute(scan_kernel, cudaFuncAttributeMaxDynamicSharedMemorySize,
                         (int)scan_smem);

    dim3 gemm_grid((T_STEPS * B_SZ) / 128, H_SZ / 128);  // (256, 2)

    // 1) xw = inputs @ W_in + b
    sgemm_k<<<gemm_grid, 256>>>(inputs, W_in, bvec, xw);

    // 2,3) ncu alignment dummies (no-ops) -> scan lands at launch #6
    align_dummy_k<<<1, 32>>>(xw);
    align_dummy_k<<<1, 32>>>(xw);

    // 4) sequential scan (64 CTAs, one per batch row)
    scan_kernel<<<B_SZ, 256, scan_smem>>>(W_rec, spike0, v0, xw,
                                          spikes, probs, vT, sT);

    // 5) preds = spikes[1:] @ W_out
    sgemm_k<<<gemm_grid, 256>>>(spikes + (size_t)B_SZ * H_SZ, W_out, nullptr, preds);
}